// round 11
// baseline (speedup 1.0000x reference)
#include <cuda_runtime.h>
#include <cuda_fp16.h>
#include <cstdint>

// out[256,64] = haar_dwt2(x[256,262144]) @ W[64,262144]^T + b
// Single fused GEMM: out = x @ W'^T + b with W' = adjoint-Haar(W) computed
// on the fly in the B loader (LDG 4 bands -> fp32 butterfly -> fp16 STS).
// mma.sync m16n8k16 fp16, fp32 accum. Grid (148): split-K 148, M=256 per CTA.
// A fp32 + XOR swizzle via cp.async; 3-stage ring, 64-col k-blocks, 512 thr.

#define IN_FEATS (1 << 18)            // 262144
#define BATCH    256
#define NOUT     64
#define KSPLIT   148
#define BK       64                   // fp32 cols per k-block (2 halves of 32)
#define NBT      (IN_FEATS / BK)      // 4096 total k-blocks
#define AHALF    32768                // A half-stage: 256 rows x 128 B
#define BSTRIDE  80
#define BHALF    (64 * BSTRIDE)       // 5120
#define HSTG     (AHALF + BHALF)      // 37888 (one 32-col half)
#define STG      (2 * HSTG)           // 75776 (one 64-col stage)
#define NSTG     3
#define SMEM_ALLOC (NSTG * STG)       // 227328

__device__ float g_part[KSPLIT * BATCH * NOUT];   // 9.7 MB split-K partials

// ---------------- helpers ----------------
__device__ __forceinline__ uint32_t smem_u32(const void* p) {
    uint32_t a;
    asm("{ .reg .u64 t; cvta.to.shared.u64 t, %1; cvt.u32.u64 %0, t; }"
        : "=r"(a) : "l"(p));
    return a;
}
__device__ __forceinline__ void cp_async16(uint32_t dst, const void* src) {
    asm volatile("cp.async.cg.shared.global [%0], [%1], 16;"
                 :: "r"(dst), "l"(src) : "memory");
}
__device__ __forceinline__ void cp_commit() {
    asm volatile("cp.async.commit_group;" ::: "memory");
}
template <int N>
__device__ __forceinline__ void cp_wait() {
    asm volatile("cp.async.wait_group %0;" :: "n"(N) : "memory");
}
__device__ __forceinline__ void mma_fp16(float* d, const uint32_t* a,
                                         const uint32_t* b) {
    asm volatile(
        "mma.sync.aligned.m16n8k16.row.col.f32.f16.f16.f32 "
        "{%0,%1,%2,%3}, {%4,%5,%6,%7}, {%8,%9}, {%0,%1,%2,%3};"
        : "+f"(d[0]), "+f"(d[1]), "+f"(d[2]), "+f"(d[3])
        : "r"(a[0]), "r"(a[1]), "r"(a[2]), "r"(a[3]), "r"(b[0]), "r"(b[1]));
}
#define LDMX4(r0, r1, r2, r3, addr)                                          \
    asm volatile("ldmatrix.sync.aligned.m8n8.x4.shared.b16 {%0,%1,%2,%3}, [%4];" \
                 : "=r"(r0), "=r"(r1), "=r"(r2), "=r"(r3) : "r"(addr))
__device__ __forceinline__ uint32_t h2u(__half2 h) { return *(uint32_t*)&h; }

// ---------- fused GEMM ----------
// Grid (148). CTA 512 thr = 16 warps, warp tile 32(m) x 32(n), M=256, N=64.
// k-blocks: 4096 = 100*28 + 48*27.
__global__ __launch_bounds__(512, 1)
void k_gemm_fused(const float* __restrict__ x, const float* __restrict__ W) {
    extern __shared__ __align__(128) char sm[];
    uint32_t sb = smem_u32(sm);
    int tid = threadIdx.x, l = tid & 31, wid = tid >> 5;
    int ks = blockIdx.x;
    int wm = wid >> 1, wn = wid & 1;

    int nb  = 27 + (ks < 100 ? 1 : 0);
    int jb0 = ks * 27 + (ks < 100 ? ks : 100);
    int k0off = jb0 * BK;

    // ---- A staging (per 32-col half): 4 rows/thread, XOR chunk swizzle ----
    int arow = tid >> 3, ac = tid & 7;
    uint32_t swz = (uint32_t)(ac ^ (arow & 7)) << 4;
    const float* a_src[4];
    uint32_t     a_dst[4];
#pragma unroll
    for (int i = 0; i < 4; i++) {
        a_src[i] = x + (size_t)(arow + 64 * i) * IN_FEATS + k0off + ac * 4;
        a_dst[i] = sb + (uint32_t)(arow + 64 * i) * 128 + swz;
    }

    // ---- B fused gather (tid<256): W' row brow, 8 cols per half ----
    bool has_b = (tid < 256);
    int brow = (tid & 255) >> 2, bc = tid & 3;
    const float* wb = W + ((size_t)brow << 18);
    uint32_t b_dst = sb + AHALF + (uint32_t)brow * BSTRIDE + bc * 16;

    float4 wf[2][4];      // [half][band]
    float  wrs = 1.0f;    // row-parity sign for the buffered jb

#define LDGW(jb)                                                            \
    do {                                                                    \
        int kbase_ = k0off + (jb) * BK;                                     \
        wrs = ((kbase_ >> 8) & 1) ? -1.0f : 1.0f;                           \
        _Pragma("unroll")                                                   \
        for (int h_ = 0; h_ < 2; h_++) {                                    \
            int kk_  = kbase_ + h_ * 32 + bc * 8;                           \
            int c_   = kk_ >> 16;                                           \
            int rr_  = (kk_ >> 8) & 255;                                    \
            int col_ = kk_ & 255;                                           \
            const float* bp_ = wb + (c_ << 16) + ((rr_ >> 1) << 7)          \
                             + (col_ >> 1);                                 \
            wf[h_][0] = *(const float4*)(bp_);                              \
            wf[h_][1] = *(const float4*)(bp_ + 16384);                      \
            wf[h_][2] = *(const float4*)(bp_ + 32768);                      \
            wf[h_][3] = *(const float4*)(bp_ + 49152);                      \
        }                                                                   \
    } while (0)

#define STSB(so)                                                            \
    do {                                                                    \
        _Pragma("unroll")                                                   \
        for (int h_ = 0; h_ < 2; h_++) {                                    \
            float e0 = wf[h_][0].x + wrs * wf[h_][1].x;                     \
            float f0 = wf[h_][2].x + wrs * wf[h_][3].x;                     \
            float e1 = wf[h_][0].y + wrs * wf[h_][1].y;                     \
            float f1 = wf[h_][2].y + wrs * wf[h_][3].y;                     \
            float e2 = wf[h_][0].z + wrs * wf[h_][1].z;                     \
            float f2 = wf[h_][2].z + wrs * wf[h_][3].z;                     \
            float e3 = wf[h_][0].w + wrs * wf[h_][1].w;                     \
            float f3 = wf[h_][2].w + wrs * wf[h_][3].w;                     \
            uint32_t u0 = h2u(__floats2half2_rn(0.5f * (e0 + f0),           \
                                                0.5f * (e0 - f0)));         \
            uint32_t u1 = h2u(__floats2half2_rn(0.5f * (e1 + f1),           \
                                                0.5f * (e1 - f1)));         \
            uint32_t u2 = h2u(__floats2half2_rn(0.5f * (e2 + f2),           \
                                                0.5f * (e2 - f2)));         \
            uint32_t u3 = h2u(__floats2half2_rn(0.5f * (e3 + f3),           \
                                                0.5f * (e3 - f3)));         \
            asm volatile("st.shared.v4.b32 [%0], {%1,%2,%3,%4};"            \
                         :: "r"(b_dst + (so) + (uint32_t)h_ * HSTG),        \
                            "r"(u0), "r"(u1), "r"(u2), "r"(u3));            \
        }                                                                   \
    } while (0)

#define ISSUE_X(jb, so)                                                     \
    do {                                                                    \
        _Pragma("unroll")                                                   \
        for (int h_ = 0; h_ < 2; h_++) {                                    \
            int ko_ = (jb) * BK + h_ * 32;                                  \
            uint32_t ho_ = (so) + (uint32_t)h_ * HSTG;                      \
            _Pragma("unroll")                                               \
            for (int i_ = 0; i_ < 4; i_++)                                  \
                cp_async16(a_dst[i_] + ho_, a_src[i_] + ko_);               \
        }                                                                   \
    } while (0)

    // ---- fragment read bases ----
    int r0 = wm * 32 + (l >> 2), q = (l & 3) * 2;
    int cb = (l >> 1) & 1, rw = r0 & 7;
    uint32_t arb = sb + (uint32_t)r0 * 128 + (l & 1) * 8;
    uint32_t lm_base = sb + AHALF
                     + (uint32_t)(wn * 32 + (l & 7) + ((l >> 4) & 1) * 8) * BSTRIDE
                     + (((l >> 3) & 1) << 4);

    float acc[2][4][4];
#pragma unroll
    for (int m = 0; m < 2; m++)
#pragma unroll
        for (int f = 0; f < 4; f++)
#pragma unroll
            for (int i = 0; i < 4; i++) acc[m][f][i] = 0.0f;

    // ---- prologue: B(0),B(1) staged; W(2) buffered; x stages 0,1 ----
    if (has_b) {
        LDGW(0); STSB(0);
        LDGW(1); STSB(STG);
        LDGW(2);
    }
    ISSUE_X(0, 0);   cp_commit();
    ISSUE_X(1, STG); cp_commit();

    uint32_t cur = 0, pre = 2 * STG;
    for (int jb = 0; jb < nb; jb++) {
        cp_wait<1>();
        __syncthreads();

        if (jb + 2 < nb) {
            if (has_b) STSB(pre);
            ISSUE_X(jb + 2, pre);
        }
        cp_commit();
        if (has_b && jb + 3 < nb) LDGW(jb + 3);

#pragma unroll
        for (int h = 0; h < 2; h++) {
            uint32_t hb = cur + (uint32_t)h * HSTG;
#pragma unroll
            for (int k0 = 0; k0 < 2; k0++) {
                uint32_t c0 = (uint32_t)((cb + 4 * k0) ^ rw) << 4;
                uint32_t c1 = (uint32_t)((cb + 4 * k0 + 2) ^ rw) << 4;
                uint32_t ah[2][4];
#pragma unroll
                for (int mf = 0; mf < 2; mf++) {
                    uint32_t base = arb + hb + (uint32_t)mf * 2048;
#pragma unroll
                    for (int i = 0; i < 4; i++) {
                        uint32_t addr = base + ((i & 1) ? 1024u : 0u)
                                      + ((i & 2) ? c1 : c0);
                        float2 v;
                        asm volatile("ld.shared.v2.f32 {%0,%1}, [%2];"
                                     : "=f"(v.x), "=f"(v.y) : "r"(addr));
                        ah[mf][i] = h2u(__floats2half2_rn(v.x, v.y));
                    }
                }
#pragma unroll
                for (int fp = 0; fp < 2; fp++) {
                    uint32_t b0, b1, b2, b3;
                    LDMX4(b0, b1, b2, b3,
                          lm_base + hb + fp * (16 * BSTRIDE) + k0 * 32);
                    uint32_t bf0[2] = {b0, b1}, bf1[2] = {b2, b3};
#pragma unroll
                    for (int mf = 0; mf < 2; mf++) {
                        mma_fp16(acc[mf][fp * 2],     ah[mf], bf0);
                        mma_fp16(acc[mf][fp * 2 + 1], ah[mf], bf1);
                    }
                }
            }
        }

        cur += STG; if (cur == NSTG * STG) cur = 0;
        pre += STG; if (pre == NSTG * STG) pre = 0;
    }

    // ---- epilogue: split-K partials ----
#pragma unroll
    for (int mf = 0; mf < 2; mf++) {
        int gm = wm * 32 + mf * 16 + (l >> 2);
        float* pb = g_part + ((size_t)ks * BATCH + gm) * NOUT;
#pragma unroll
        for (int f = 0; f < 4; f++) {
            int n = wn * 32 + f * 8 + q;
            *(float2*)(pb + n) =
                make_float2(acc[mf][f][0], acc[mf][f][1]);
            *(float2*)(pb + 8 * NOUT + n) =
                make_float2(acc[mf][f][2], acc[mf][f][3]);
        }
    }
}

// ---------- reduce split-K partials + bias ----------
__global__ __launch_bounds__(256) void k_reduce(const float* __restrict__ bias,
                                                float* __restrict__ out) {
    int t = blockIdx.x * 256 + threadIdx.x;     // 0..16383
    float s = bias[t & (NOUT - 1)];
    const float* p = g_part + t;
#pragma unroll 4
    for (int ks = 0; ks < KSPLIT; ks++)
        s += p[(size_t)ks * BATCH * NOUT];
    out[t] = s;
}

extern "C" void kernel_launch(void* const* d_in, const int* in_sizes, int n_in,
                              void* d_out, int out_size) {
    const float* x = (const float*)d_in[0];
    const float* W = (const float*)d_in[1];
    const float* b = (const float*)d_in[2];

    cudaFuncSetAttribute(k_gemm_fused, cudaFuncAttributeMaxDynamicSharedMemorySize,
                         SMEM_ALLOC);

    k_gemm_fused<<<KSPLIT, 512, SMEM_ALLOC>>>(x, W);
    k_reduce<<<(BATCH * NOUT) / 256, 256>>>(b, (float*)d_out);
}

// round 12
// speedup vs baseline: 1.0865x; 1.0865x over previous
#include <cuda_runtime.h>
#include <cuda_fp16.h>
#include <cstdint>

// out[256,64] = haar_dwt2(x[256,262144]) @ W[64,262144]^T + b
// Single fused GEMM: out = x @ W'^T + b with W' = adjoint-Haar(W) computed
// on the fly in the B loader (LDG 4 bands -> fp32 butterfly -> fp16 STS).
// mma.sync m16n8k16 fp16, fp32 accum. Grid (148): split-K 148, M=256 per CTA.
// A fp32 + XOR swizzle via cp.async; 3-stage ring, 64-col k-blocks, 512 thr.
// Two-stage deterministic split-K reduction (148 = 4 x 37).

#define IN_FEATS (1 << 18)            // 262144
#define BATCH    256
#define NOUT     64
#define KSPLIT   148
#define BK       64                   // fp32 cols per k-block (2 halves of 32)
#define NBT      (IN_FEATS / BK)      // 4096 total k-blocks
#define AHALF    32768                // A half-stage: 256 rows x 128 B
#define BSTRIDE  80
#define BHALF    (64 * BSTRIDE)       // 5120
#define HSTG     (AHALF + BHALF)      // 37888 (one 32-col half)
#define STG      (2 * HSTG)           // 75776 (one 64-col stage)
#define NSTG     3
#define SMEM_ALLOC (NSTG * STG)       // 227328
#define OUTELEMS (BATCH * NOUT)       // 16384

__device__ float g_part[KSPLIT * OUTELEMS];   // 9.7 MB split-K partials
__device__ float g_part2[4 * OUTELEMS];       // 256 KB stage-1 sums

// ---------------- helpers ----------------
__device__ __forceinline__ uint32_t smem_u32(const void* p) {
    uint32_t a;
    asm("{ .reg .u64 t; cvta.to.shared.u64 t, %1; cvt.u32.u64 %0, t; }"
        : "=r"(a) : "l"(p));
    return a;
}
__device__ __forceinline__ void cp_async16(uint32_t dst, const void* src) {
    asm volatile("cp.async.cg.shared.global [%0], [%1], 16;"
                 :: "r"(dst), "l"(src) : "memory");
}
__device__ __forceinline__ void cp_commit() {
    asm volatile("cp.async.commit_group;" ::: "memory");
}
template <int N>
__device__ __forceinline__ void cp_wait() {
    asm volatile("cp.async.wait_group %0;" :: "n"(N) : "memory");
}
__device__ __forceinline__ void mma_fp16(float* d, const uint32_t* a,
                                         const uint32_t* b) {
    asm volatile(
        "mma.sync.aligned.m16n8k16.row.col.f32.f16.f16.f32 "
        "{%0,%1,%2,%3}, {%4,%5,%6,%7}, {%8,%9}, {%0,%1,%2,%3};"
        : "+f"(d[0]), "+f"(d[1]), "+f"(d[2]), "+f"(d[3])
        : "r"(a[0]), "r"(a[1]), "r"(a[2]), "r"(a[3]), "r"(b[0]), "r"(b[1]));
}
#define LDMX4(r0, r1, r2, r3, addr)                                          \
    asm volatile("ldmatrix.sync.aligned.m8n8.x4.shared.b16 {%0,%1,%2,%3}, [%4];" \
                 : "=r"(r0), "=r"(r1), "=r"(r2), "=r"(r3) : "r"(addr))
__device__ __forceinline__ uint32_t h2u(__half2 h) { return *(uint32_t*)&h; }

// ---------- fused GEMM ----------
// Grid (148). CTA 512 thr = 16 warps, warp tile 32(m) x 32(n), M=256, N=64.
// k-blocks: 4096 = 100*28 + 48*27.
__global__ __launch_bounds__(512, 1)
void k_gemm_fused(const float* __restrict__ x, const float* __restrict__ W) {
    extern __shared__ __align__(128) char sm[];
    uint32_t sb = smem_u32(sm);
    int tid = threadIdx.x, l = tid & 31, wid = tid >> 5;
    int ks = blockIdx.x;
    int wm = wid >> 1, wn = wid & 1;

    int nb  = 27 + (ks < 100 ? 1 : 0);
    int jb0 = ks * 27 + (ks < 100 ? ks : 100);
    int k0off = jb0 * BK;

    // ---- A staging (per 32-col half): 4 rows/thread, XOR chunk swizzle ----
    int arow = tid >> 3, ac = tid & 7;
    uint32_t swz = (uint32_t)(ac ^ (arow & 7)) << 4;
    const float* a_src[4];
    uint32_t     a_dst[4];
#pragma unroll
    for (int i = 0; i < 4; i++) {
        a_src[i] = x + (size_t)(arow + 64 * i) * IN_FEATS + k0off + ac * 4;
        a_dst[i] = sb + (uint32_t)(arow + 64 * i) * 128 + swz;
    }

    // ---- B fused gather (tid<256): W' row brow, 8 cols per half ----
    bool has_b = (tid < 256);
    int brow = (tid & 255) >> 2, bc = tid & 3;
    const float* wb = W + ((size_t)brow << 18);
    uint32_t b_dst = sb + AHALF + (uint32_t)brow * BSTRIDE + bc * 16;

    float4 wf[2][4];      // [half][band]
    float  wrs = 1.0f;    // row-parity sign for the buffered jb

#define LDGW(jb)                                                            \
    do {                                                                    \
        int kbase_ = k0off + (jb) * BK;                                     \
        wrs = ((kbase_ >> 8) & 1) ? -1.0f : 1.0f;                           \
        _Pragma("unroll")                                                   \
        for (int h_ = 0; h_ < 2; h_++) {                                    \
            int kk_  = kbase_ + h_ * 32 + bc * 8;                           \
            int c_   = kk_ >> 16;                                           \
            int rr_  = (kk_ >> 8) & 255;                                    \
            int col_ = kk_ & 255;                                           \
            const float* bp_ = wb + (c_ << 16) + ((rr_ >> 1) << 7)          \
                             + (col_ >> 1);                                 \
            wf[h_][0] = *(const float4*)(bp_);                              \
            wf[h_][1] = *(const float4*)(bp_ + 16384);                      \
            wf[h_][2] = *(const float4*)(bp_ + 32768);                      \
            wf[h_][3] = *(const float4*)(bp_ + 49152);                      \
        }                                                                   \
    } while (0)

#define STSB(so)                                                            \
    do {                                                                    \
        _Pragma("unroll")                                                   \
        for (int h_ = 0; h_ < 2; h_++) {                                    \
            float e0 = wf[h_][0].x + wrs * wf[h_][1].x;                     \
            float f0 = wf[h_][2].x + wrs * wf[h_][3].x;                     \
            float e1 = wf[h_][0].y + wrs * wf[h_][1].y;                     \
            float f1 = wf[h_][2].y + wrs * wf[h_][3].y;                     \
            float e2 = wf[h_][0].z + wrs * wf[h_][1].z;                     \
            float f2 = wf[h_][2].z + wrs * wf[h_][3].z;                     \
            float e3 = wf[h_][0].w + wrs * wf[h_][1].w;                     \
            float f3 = wf[h_][2].w + wrs * wf[h_][3].w;                     \
            uint32_t u0 = h2u(__floats2half2_rn(0.5f * (e0 + f0),           \
                                                0.5f * (e0 - f0)));         \
            uint32_t u1 = h2u(__floats2half2_rn(0.5f * (e1 + f1),           \
                                                0.5f * (e1 - f1)));         \
            uint32_t u2 = h2u(__floats2half2_rn(0.5f * (e2 + f2),           \
                                                0.5f * (e2 - f2)));         \
            uint32_t u3 = h2u(__floats2half2_rn(0.5f * (e3 + f3),           \
                                                0.5f * (e3 - f3)));         \
            asm volatile("st.shared.v4.b32 [%0], {%1,%2,%3,%4};"            \
                         :: "r"(b_dst + (so) + (uint32_t)h_ * HSTG),        \
                            "r"(u0), "r"(u1), "r"(u2), "r"(u3));            \
        }                                                                   \
    } while (0)

#define ISSUE_X(jb, so)                                                     \
    do {                                                                    \
        _Pragma("unroll")                                                   \
        for (int h_ = 0; h_ < 2; h_++) {                                    \
            int ko_ = (jb) * BK + h_ * 32;                                  \
            uint32_t ho_ = (so) + (uint32_t)h_ * HSTG;                      \
            _Pragma("unroll")                                               \
            for (int i_ = 0; i_ < 4; i_++)                                  \
                cp_async16(a_dst[i_] + ho_, a_src[i_] + ko_);               \
        }                                                                   \
    } while (0)

    // ---- fragment read bases ----
    int r0 = wm * 32 + (l >> 2), q = (l & 3) * 2;
    int cb = (l >> 1) & 1, rw = r0 & 7;
    uint32_t arb = sb + (uint32_t)r0 * 128 + (l & 1) * 8;
    uint32_t lm_base = sb + AHALF
                     + (uint32_t)(wn * 32 + (l & 7) + ((l >> 4) & 1) * 8) * BSTRIDE
                     + (((l >> 3) & 1) << 4);

    float acc[2][4][4];
#pragma unroll
    for (int m = 0; m < 2; m++)
#pragma unroll
        for (int f = 0; f < 4; f++)
#pragma unroll
            for (int i = 0; i < 4; i++) acc[m][f][i] = 0.0f;

    // ---- prologue: B(0),B(1) staged; W(2) buffered; x stages 0,1 ----
    if (has_b) {
        LDGW(0); STSB(0);
        LDGW(1); STSB(STG);
        LDGW(2);
    }
    ISSUE_X(0, 0);   cp_commit();
    ISSUE_X(1, STG); cp_commit();

    uint32_t cur = 0, pre = 2 * STG;
    for (int jb = 0; jb < nb; jb++) {
        cp_wait<1>();
        __syncthreads();

        if (jb + 2 < nb) {
            if (has_b) STSB(pre);
            ISSUE_X(jb + 2, pre);
        }
        cp_commit();
        if (has_b && jb + 3 < nb) LDGW(jb + 3);

#pragma unroll
        for (int h = 0; h < 2; h++) {
            uint32_t hb = cur + (uint32_t)h * HSTG;
#pragma unroll
            for (int k0 = 0; k0 < 2; k0++) {
                uint32_t c0 = (uint32_t)((cb + 4 * k0) ^ rw) << 4;
                uint32_t c1 = (uint32_t)((cb + 4 * k0 + 2) ^ rw) << 4;
                uint32_t ah[2][4];
#pragma unroll
                for (int mf = 0; mf < 2; mf++) {
                    uint32_t base = arb + hb + (uint32_t)mf * 2048;
#pragma unroll
                    for (int i = 0; i < 4; i++) {
                        uint32_t addr = base + ((i & 1) ? 1024u : 0u)
                                      + ((i & 2) ? c1 : c0);
                        float2 v;
                        asm volatile("ld.shared.v2.f32 {%0,%1}, [%2];"
                                     : "=f"(v.x), "=f"(v.y) : "r"(addr));
                        ah[mf][i] = h2u(__floats2half2_rn(v.x, v.y));
                    }
                }
#pragma unroll
                for (int fp = 0; fp < 2; fp++) {
                    uint32_t b0, b1, b2, b3;
                    LDMX4(b0, b1, b2, b3,
                          lm_base + hb + fp * (16 * BSTRIDE) + k0 * 32);
                    uint32_t bf0[2] = {b0, b1}, bf1[2] = {b2, b3};
#pragma unroll
                    for (int mf = 0; mf < 2; mf++) {
                        mma_fp16(acc[mf][fp * 2],     ah[mf], bf0);
                        mma_fp16(acc[mf][fp * 2 + 1], ah[mf], bf1);
                    }
                }
            }
        }

        cur += STG; if (cur == NSTG * STG) cur = 0;
        pre += STG; if (pre == NSTG * STG) pre = 0;
    }

    // ---- epilogue: split-K partials ----
#pragma unroll
    for (int mf = 0; mf < 2; mf++) {
        int gm = wm * 32 + mf * 16 + (l >> 2);
        float* pb = g_part + ((size_t)ks * BATCH + gm) * NOUT;
#pragma unroll
        for (int f = 0; f < 4; f++) {
            int n = wn * 32 + f * 8 + q;
            *(float2*)(pb + n) =
                make_float2(acc[mf][f][0], acc[mf][f][1]);
            *(float2*)(pb + 8 * NOUT + n) =
                make_float2(acc[mf][f][2], acc[mf][f][3]);
        }
    }
}

// ---------- reduce stage 1: 148 -> 4 (each block-row sums 37 chunks) ----------
__global__ __launch_bounds__(256) void k_reduce1() {
    int t = blockIdx.x * 256 + threadIdx.x;       // 0..16383
    int p = blockIdx.y;                           // 0..3
    const float* src = g_part + (size_t)p * 37 * OUTELEMS + t;
    float s = 0.0f;
#pragma unroll
    for (int i = 0; i < 37; i++)
        s += src[(size_t)i * OUTELEMS];
    g_part2[p * OUTELEMS + t] = s;
}

// ---------- reduce stage 2: 4 sums + bias ----------
__global__ __launch_bounds__(256) void k_reduce2(const float* __restrict__ bias,
                                                 float* __restrict__ out) {
    int t = blockIdx.x * 256 + threadIdx.x;       // 0..16383
    float s = bias[t & (NOUT - 1)];
    s += g_part2[t];
    s += g_part2[OUTELEMS + t];
    s += g_part2[2 * OUTELEMS + t];
    s += g_part2[3 * OUTELEMS + t];
    out[t] = s;
}

extern "C" void kernel_launch(void* const* d_in, const int* in_sizes, int n_in,
                              void* d_out, int out_size) {
    const float* x = (const float*)d_in[0];
    const float* W = (const float*)d_in[1];
    const float* b = (const float*)d_in[2];

    cudaFuncSetAttribute(k_gemm_fused, cudaFuncAttributeMaxDynamicSharedMemorySize,
                         SMEM_ALLOC);

    k_gemm_fused<<<KSPLIT, 512, SMEM_ALLOC>>>(x, W);
    k_reduce1<<<dim3(OUTELEMS / 256, 4), 256>>>();
    k_reduce2<<<OUTELEMS / 256, 256>>>(b, (float*)d_out);
}